// round 1
// baseline (speedup 1.0000x reference)
#include <cuda_runtime.h>

// FeedForwardAttention — algebraically reduced.
//
// attns[b,q,k] = softmax_k(fq[b,q] + fk[b,k]) = softmax_k(fk[b,k])  (shift invariance)
// fk[b,l] = (Wk^T fck_w) . key[b,l]  (+const, cancels)
// out[b,q,:] = Wv @ (sum_k p[b,k] * value[b,k,:]) + bv   (independent of q)
//
// Memory: read key 64MB, read value 64MB, write out 64MB  -> HBM bound.

#define BB 8
#define LL 2048
#define CC 1024
#define NROWS (BB * LL)          // 16384
#define NCHUNK 32
#define KCHUNK (LL / NCHUNK)     // 64

__device__ float g_u[CC];                      // Wk^T fck_w
__device__ float g_fk[NROWS];                  // per-position score
__device__ float g_p[NROWS];                   // softmax weights
__device__ float g_part[NCHUNK * BB * CC];     // partial weighted value sums
__device__ float g_vbar[BB * CC];              // sum_k p * value
__device__ float g_outs[BB * CC];              // Wv @ vbar + bv

// ---- kernel 0: u[c] = sum_o fck_w[o] * Wk[o, c] ----------------------------
__global__ void k_u(const float* __restrict__ Wk, const float* __restrict__ fckw) {
    int c = blockIdx.x * blockDim.x + threadIdx.x;   // 0..1023
    float acc = 0.f;
#pragma unroll 4
    for (int o = 0; o < CC; ++o)
        acc += fckw[o] * Wk[(size_t)o * CC + c];     // coalesced in c
    g_u[c] = acc;
}

// ---- kernel 1: fk[row] = u . key[row, :]  (one warp per row) ---------------
__global__ void k_fk(const float* __restrict__ key) {
    int warp = threadIdx.x >> 5, lane = threadIdx.x & 31;
    int row = blockIdx.x * 8 + warp;                 // 16384 rows
    const float4* kp = (const float4*)(key + (size_t)row * CC);
    const float4* up = (const float4*)g_u;
    float acc = 0.f;
#pragma unroll
    for (int i = 0; i < 8; ++i) {
        int idx = lane + i * 32;                     // 256 float4 per row
        float4 kv = kp[idx];
        float4 uv = up[idx];
        acc += kv.x * uv.x + kv.y * uv.y + kv.z * uv.z + kv.w * uv.w;
    }
#pragma unroll
    for (int o = 16; o; o >>= 1) acc += __shfl_xor_sync(0xFFFFFFFFu, acc, o);
    if (lane == 0) g_fk[row] = acc;
}

// ---- kernel 2: softmax over k per batch (block = 1024 threads, 2 elems each)
__global__ void k_softmax() {
    __shared__ float red[1024];
    int b = blockIdx.x, t = threadIdx.x;
    float f0 = g_fk[b * LL + t];
    float f1 = g_fk[b * LL + t + 1024];
    float m = fmaxf(f0, f1);
    red[t] = m; __syncthreads();
    for (int s = 512; s; s >>= 1) {
        if (t < s) red[t] = fmaxf(red[t], red[t + s]);
        __syncthreads();
    }
    m = red[0]; __syncthreads();
    float e0 = __expf(f0 - m), e1 = __expf(f1 - m);
    red[t] = e0 + e1; __syncthreads();
    for (int s = 512; s; s >>= 1) {
        if (t < s) red[t] += red[t + s];
        __syncthreads();
    }
    float inv = 1.f / red[0];
    g_p[b * LL + t]        = e0 * inv;
    g_p[b * LL + t + 1024] = e1 * inv;
}

// ---- kernel 3: partial v̄: each block = (chunk of 64 k-rows, batch b) -------
__global__ void k_vbar_part(const float* __restrict__ value) {
    int chunk = blockIdx.x, b = blockIdx.y, t = threadIdx.x;   // t: 0..255 (float4 slot)
    __shared__ float sp[KCHUNK];
    int k0 = chunk * KCHUNK;
    if (t < KCHUNK) sp[t] = g_p[b * LL + k0 + t];
    __syncthreads();
    const float4* vp = (const float4*)(value + (size_t)(b * LL + k0) * CC);
    float4 acc = make_float4(0.f, 0.f, 0.f, 0.f);
#pragma unroll 4
    for (int k = 0; k < KCHUNK; ++k) {
        float p = sp[k];
        float4 v = vp[(size_t)k * (CC / 4) + t];
        acc.x += p * v.x; acc.y += p * v.y; acc.z += p * v.z; acc.w += p * v.w;
    }
    ((float4*)g_part)[(size_t)(chunk * BB + b) * (CC / 4) + t] = acc;
}

// ---- kernel 4: deterministic partial reduce --------------------------------
__global__ void k_vbar_reduce() {
    int i = blockIdx.x * blockDim.x + threadIdx.x;   // 0..8191
    float acc = 0.f;
#pragma unroll
    for (int ch = 0; ch < NCHUNK; ++ch)
        acc += g_part[(size_t)ch * (BB * CC) + i];
    g_vbar[i] = acc;
}

// ---- kernel 5: outs[b,d] = Wv[d,:] . vbar[b,:] + bv[d]  (warp per d) -------
__global__ void k_out(const float* __restrict__ Wv, const float* __restrict__ bv) {
    int warp = threadIdx.x >> 5, lane = threadIdx.x & 31;
    int d = blockIdx.x * 8 + warp;                   // 1024 rows of Wv
    const float4* wp = (const float4*)(Wv + (size_t)d * CC);
    const float4* vb = (const float4*)g_vbar;
    float acc[BB];
#pragma unroll
    for (int b = 0; b < BB; ++b) acc[b] = 0.f;
#pragma unroll
    for (int i = 0; i < 8; ++i) {
        int idx = lane + i * 32;
        float4 w = wp[idx];
#pragma unroll
        for (int b = 0; b < BB; ++b) {
            float4 v = vb[b * (CC / 4) + idx];
            acc[b] += w.x * v.x + w.y * v.y + w.z * v.z + w.w * v.w;
        }
    }
#pragma unroll
    for (int b = 0; b < BB; ++b)
#pragma unroll
        for (int o = 16; o; o >>= 1) acc[b] += __shfl_xor_sync(0xFFFFFFFFu, acc[b], o);
    if (lane == 0) {
        float bias = bv[d];
#pragma unroll
        for (int b = 0; b < BB; ++b) g_outs[b * CC + d] = acc[b] + bias;
    }
}

// ---- kernel 6: broadcast outs[b,:] to all 2048 q rows ----------------------
__global__ void k_bcast(float4* __restrict__ out) {
    int i = blockIdx.x * blockDim.x + threadIdx.x;   // float4 index, 4,194,304 total
    int b  = i >> 19;                                // 524288 float4 per batch
    int d4 = i & 255;                                // 256 float4 per out row
    out[i] = ((const float4*)g_outs)[b * 256 + d4];
}

extern "C" void kernel_launch(void* const* d_in, const int* in_sizes, int n_in,
                              void* d_out, int out_size) {
    // metadata order: 0 query, 1 key, 2 value, 3 Wq, 4 bq, 5 Wk, 6 bk,
    //                 7 Wv, 8 bv, 9 fcq_w, 10 fcq_b, 11 fck_w, 12 fck_b
    const float* key   = (const float*)d_in[1];
    const float* value = (const float*)d_in[2];
    const float* Wk    = (const float*)d_in[5];
    const float* Wv    = (const float*)d_in[7];
    const float* bv    = (const float*)d_in[8];
    const float* fckw  = (const float*)d_in[11];

    k_u<<<CC / 256, 256>>>(Wk, fckw);
    k_fk<<<NROWS / 8, 256>>>(key);
    k_softmax<<<BB, 1024>>>();
    dim3 gpart(NCHUNK, BB);
    k_vbar_part<<<gpart, 256>>>(value);
    k_vbar_reduce<<<(BB * CC) / 256, 256>>>();
    k_out<<<CC / 8, 256>>>(Wv, bv);
    k_bcast<<<(BB * LL * CC / 4) / 256, 256>>>((float4*)d_out);
}

// round 2
// speedup vs baseline: 2.8757x; 2.8757x over previous
#include <cuda_runtime.h>

// FeedForwardAttention — algebraically reduced.
// attns[b,q,k] = softmax_k(fk[b,k])  (softmax shift-invariance kills fq)
// fk[b,l] = (Wk^T fck_w) . key[b,l]
// out[b,q,:] = Wv @ (sum_k p[b,k] * value[b,k,:]) + bv   (independent of q)
// HBM floor: read key 64MB + value 64MB, write out 64MB.

#define BB 8
#define LL 2048
#define CC 1024
#define NROWS (BB * LL)          // 16384
#define NCHUNK 64
#define KCHUNK (LL / NCHUNK)     // 32
#define UOC 16                   // o-chunks for u partials

__device__ float g_upart[UOC * CC];
__device__ float g_u[CC];
__device__ float g_fk[NROWS];
__device__ float g_p[NROWS];
__device__ float g_part[NCHUNK * BB * CC];
__device__ float g_vbar[BB * CC];
__device__ float g_outs[BB * CC];

// ---- kernel 0a: partial u: block (cx, oc) sums 64 o-rows for 256 c ---------
__global__ void k_u_part(const float* __restrict__ Wk, const float* __restrict__ fckw) {
    int c  = blockIdx.x * 256 + threadIdx.x;
    int oc = blockIdx.y;                              // 16 chunks of 64 rows
    int o0 = oc * (CC / UOC);
    float acc = 0.f;
#pragma unroll 8
    for (int o = 0; o < CC / UOC; ++o)
        acc += fckw[o0 + o] * Wk[(size_t)(o0 + o) * CC + c];
    g_upart[oc * CC + c] = acc;
}

// ---- kernel 0b: reduce 16 partials -----------------------------------------
__global__ void k_u_reduce() {
    int c = blockIdx.x * 256 + threadIdx.x;
    float acc = 0.f;
#pragma unroll
    for (int oc = 0; oc < UOC; ++oc) acc += g_upart[oc * CC + c];
    g_u[c] = acc;
}

// ---- kernel 1: fk[row] = u . key[row, :]  (one warp per row) ---------------
__global__ void k_fk(const float* __restrict__ key) {
    int warp = threadIdx.x >> 5, lane = threadIdx.x & 31;
    int row = blockIdx.x * 8 + warp;                  // 16384 rows
    const float4* kp = (const float4*)(key + (size_t)row * CC);
    const float4* up = (const float4*)g_u;
    float acc = 0.f;
#pragma unroll
    for (int i = 0; i < 8; ++i) {
        int idx = lane + i * 32;                      // 256 float4 per row
        float4 kv = kp[idx];
        float4 uv = up[idx];
        acc += kv.x * uv.x + kv.y * uv.y + kv.z * uv.z + kv.w * uv.w;
    }
#pragma unroll
    for (int o = 16; o; o >>= 1) acc += __shfl_xor_sync(0xFFFFFFFFu, acc, o);
    if (lane == 0) g_fk[row] = acc;
}

// ---- kernel 2: softmax over k per batch ------------------------------------
__global__ void k_softmax() {
    __shared__ float red[1024];
    int b = blockIdx.x, t = threadIdx.x;
    float f0 = g_fk[b * LL + t];
    float f1 = g_fk[b * LL + t + 1024];
    float m = fmaxf(f0, f1);
    red[t] = m; __syncthreads();
    for (int s = 512; s; s >>= 1) {
        if (t < s) red[t] = fmaxf(red[t], red[t + s]);
        __syncthreads();
    }
    m = red[0]; __syncthreads();
    float e0 = __expf(f0 - m), e1 = __expf(f1 - m);
    red[t] = e0 + e1; __syncthreads();
    for (int s = 512; s; s >>= 1) {
        if (t < s) red[t] += red[t + s];
        __syncthreads();
    }
    float inv = 1.f / red[0];
    g_p[b * LL + t]        = e0 * inv;
    g_p[b * LL + t + 1024] = e1 * inv;
}

// ---- kernel 3: partial v̄: block = (chunk of 32 k-rows, batch b) ------------
__global__ void k_vbar_part(const float* __restrict__ value) {
    int chunk = blockIdx.x, b = blockIdx.y, t = threadIdx.x;   // t: float4 slot
    __shared__ float sp[KCHUNK];
    int k0 = chunk * KCHUNK;
    if (t < KCHUNK) sp[t] = g_p[b * LL + k0 + t];
    __syncthreads();
    const float4* vp = (const float4*)(value + (size_t)(b * LL + k0) * CC);
    float4 acc = make_float4(0.f, 0.f, 0.f, 0.f);
#pragma unroll 8
    for (int k = 0; k < KCHUNK; ++k) {
        float p = sp[k];
        float4 v = vp[(size_t)k * (CC / 4) + t];
        acc.x += p * v.x; acc.y += p * v.y; acc.z += p * v.z; acc.w += p * v.w;
    }
    ((float4*)g_part)[(size_t)(chunk * BB + b) * (CC / 4) + t] = acc;
}

// ---- kernel 4: deterministic partial reduce --------------------------------
__global__ void k_vbar_reduce() {
    int i = blockIdx.x * blockDim.x + threadIdx.x;   // 0..8191
    float acc = 0.f;
#pragma unroll
    for (int ch = 0; ch < NCHUNK; ++ch)
        acc += g_part[(size_t)ch * (BB * CC) + i];
    g_vbar[i] = acc;
}

// ---- kernel 5: outs[b,d] = Wv[d,:] . vbar[b,:] + bv[d]  (warp per d) -------
__global__ void k_out(const float* __restrict__ Wv, const float* __restrict__ bv) {
    int warp = threadIdx.x >> 5, lane = threadIdx.x & 31;
    int d = blockIdx.x * 8 + warp;
    const float4* wp = (const float4*)(Wv + (size_t)d * CC);
    const float4* vb = (const float4*)g_vbar;
    float acc[BB];
#pragma unroll
    for (int b = 0; b < BB; ++b) acc[b] = 0.f;
#pragma unroll
    for (int i = 0; i < 8; ++i) {
        int idx = lane + i * 32;
        float4 w = wp[idx];
#pragma unroll
        for (int b = 0; b < BB; ++b) {
            float4 v = vb[b * (CC / 4) + idx];
            acc[b] += w.x * v.x + w.y * v.y + w.z * v.z + w.w * v.w;
        }
    }
#pragma unroll
    for (int b = 0; b < BB; ++b)
#pragma unroll
        for (int o = 16; o; o >>= 1) acc[b] += __shfl_xor_sync(0xFFFFFFFFu, acc[b], o);
    if (lane == 0) {
        float bias = bv[d];
#pragma unroll
        for (int b = 0; b < BB; ++b) g_outs[b * CC + d] = acc[b] + bias;
    }
}

// ---- kernel 6: broadcast outs[b,:] to all 2048 q rows ----------------------
__global__ void k_bcast(float4* __restrict__ out) {
    int i = blockIdx.x * blockDim.x + threadIdx.x;   // float4 index
    int b  = i >> 19;                                // 524288 float4 per batch
    int d4 = i & 255;                                // 256 float4 per out row
    out[i] = ((const float4*)g_outs)[b * 256 + d4];
}

extern "C" void kernel_launch(void* const* d_in, const int* in_sizes, int n_in,
                              void* d_out, int out_size) {
    const float* key   = (const float*)d_in[1];
    const float* value = (const float*)d_in[2];
    const float* Wk    = (const float*)d_in[5];
    const float* Wv    = (const float*)d_in[7];
    const float* bv    = (const float*)d_in[8];
    const float* fckw  = (const float*)d_in[11];

    dim3 gu(CC / 256, UOC);
    k_u_part<<<gu, 256>>>(Wk, fckw);
    k_u_reduce<<<CC / 256, 256>>>();
    k_fk<<<NROWS / 8, 256>>>(key);
    k_softmax<<<BB, 1024>>>();
    dim3 gpart(NCHUNK, BB);
    k_vbar_part<<<gpart, 256>>>(value);
    k_vbar_reduce<<<(BB * CC) / 256, 256>>>();
    k_out<<<CC / 8, 256>>>(Wv, bv);
    k_bcast<<<(BB * LL * CC / 4) / 256, 256>>>((float4*)d_out);
}